// round 2
// baseline (speedup 1.0000x reference)
#include <cuda_runtime.h>

#define DIMC 768
#define NSEQ 1024
#define BATCH 8
#define NH 12
#define DH 64
#define ATT_SCALE 0.125f   // 64^-0.5

// ---------------- scratch (static device globals; no allocation) ------------
__device__ float g_qh [BATCH*NH*NSEQ*DH];   // [b][h][n][d]
__device__ float g_kh [BATCH*NH*NSEQ*DH];
__device__ float g_vh [BATCH*NH*NSEQ*DH];
__device__ float g_vih[BATCH*NH*NSEQ*DH];
__device__ float g_o1 [BATCH*NSEQ*DIMC];    // merged [b][n][c]
__device__ float g_o2 [BATCH*NSEQ*DIMC];

// ---------------------------------------------------------------------------
// Input projection: C[m,o] = sum_k in[n,b,k] * W[o,k], m = b*NSEQ+n
// in is seq-first [NSEQ, BATCH, DIMC]. Output written head-major:
// out[((b*NH+h)*NSEQ + n)*DH + d],  o = h*DH + d.
// Block: 64(m) x 64(o) tile, 256 threads, 4x4 micro-tile, K-step 16.
// ---------------------------------------------------------------------------
__global__ __launch_bounds__(256) void proj_in_kernel(
    const float* __restrict__ in, const float* __restrict__ W,
    float* __restrict__ out)
{
    __shared__ float As[16][68];
    __shared__ float Ws[16][68];
    const int h  = blockIdx.x;          // 0..11 (output 64-col tile)
    const int m0 = blockIdx.y * 64;     // row tile
    const int b  = m0 / NSEQ;
    const int n0 = m0 % NSEQ;
    const int tid = threadIdx.x;
    const int tx = tid & 15, ty = tid >> 4;
    const int lm = tid >> 2;            // 0..63
    const int lk = (tid & 3) * 4;       // 0,4,8,12

    float acc[4][4] = {};
    const float* aptr = in + ((size_t)(n0 + lm) * BATCH + b) * DIMC + lk;
    const float* wptr = W  + ((size_t)(h * DH + lm)) * DIMC + lk;

    for (int k0 = 0; k0 < DIMC; k0 += 16) {
        float4 a = *(const float4*)(aptr + k0);
        float4 w = *(const float4*)(wptr + k0);
        As[lk+0][lm]=a.x; As[lk+1][lm]=a.y; As[lk+2][lm]=a.z; As[lk+3][lm]=a.w;
        Ws[lk+0][lm]=w.x; Ws[lk+1][lm]=w.y; Ws[lk+2][lm]=w.z; Ws[lk+3][lm]=w.w;
        __syncthreads();
        #pragma unroll
        for (int k = 0; k < 16; k++) {
            float4 av = *(const float4*)&As[k][ty*4];
            float4 wv = *(const float4*)&Ws[k][tx*4];
            float ar[4] = {av.x,av.y,av.z,av.w};
            float wr[4] = {wv.x,wv.y,wv.z,wv.w};
            #pragma unroll
            for (int i = 0; i < 4; i++)
                #pragma unroll
                for (int j = 0; j < 4; j++) acc[i][j] += ar[i]*wr[j];
        }
        __syncthreads();
    }
    #pragma unroll
    for (int i = 0; i < 4; i++) {
        float4 v = make_float4(acc[i][0],acc[i][1],acc[i][2],acc[i][3]);
        *(float4*)&out[(((size_t)b*NH + h)*NSEQ + n0 + 4*ty + i)*DH + 4*tx] = v;
    }
}

// ---------------------------------------------------------------------------
// Output projection: out[m, o] = sum_k A[m,k]*W[o,k] + bias[o]
// A row-major [8192, 768], out row-major [8192, 768].
// ---------------------------------------------------------------------------
__global__ __launch_bounds__(256) void proj_out_kernel(
    const float* __restrict__ A, const float* __restrict__ W,
    const float* __restrict__ bias, float* __restrict__ out)
{
    __shared__ float As[16][68];
    __shared__ float Ws[16][68];
    const int h  = blockIdx.x;
    const int m0 = blockIdx.y * 64;
    const int tid = threadIdx.x;
    const int tx = tid & 15, ty = tid >> 4;
    const int lm = tid >> 2;
    const int lk = (tid & 3) * 4;

    float acc[4][4] = {};
    const float* aptr = A + (size_t)(m0 + lm) * DIMC + lk;
    const float* wptr = W + ((size_t)(h * DH + lm)) * DIMC + lk;

    for (int k0 = 0; k0 < DIMC; k0 += 16) {
        float4 a = *(const float4*)(aptr + k0);
        float4 w = *(const float4*)(wptr + k0);
        As[lk+0][lm]=a.x; As[lk+1][lm]=a.y; As[lk+2][lm]=a.z; As[lk+3][lm]=a.w;
        Ws[lk+0][lm]=w.x; Ws[lk+1][lm]=w.y; Ws[lk+2][lm]=w.z; Ws[lk+3][lm]=w.w;
        __syncthreads();
        #pragma unroll
        for (int k = 0; k < 16; k++) {
            float4 av = *(const float4*)&As[k][ty*4];
            float4 wv = *(const float4*)&Ws[k][tx*4];
            float ar[4] = {av.x,av.y,av.z,av.w};
            float wr[4] = {wv.x,wv.y,wv.z,wv.w};
            #pragma unroll
            for (int i = 0; i < 4; i++)
                #pragma unroll
                for (int j = 0; j < 4; j++) acc[i][j] += ar[i]*wr[j];
        }
        __syncthreads();
    }
    float4 bv = *(const float4*)&bias[h*DH + 4*tx];
    float br[4] = {bv.x,bv.y,bv.z,bv.w};
    #pragma unroll
    for (int i = 0; i < 4; i++) {
        float4 v = make_float4(acc[i][0]+br[0],acc[i][1]+br[1],
                               acc[i][2]+br[2],acc[i][3]+br[3]);
        *(float4*)&out[(size_t)(m0 + 4*ty + i)*DIMC + h*DH + 4*tx] = v;
    }
}

// ---------------------------------------------------------------------------
// Flash attention with DUAL value streams (softmax computed once, applied to
// both V and V_img). One block = one (b,h) x 64-query-row tile.
// Online softmax stats kept replicated in registers of the 16 threads that
// own each row (shuffle reductions within the 16-lane half-warp).
// ---------------------------------------------------------------------------
__global__ __launch_bounds__(256) void attn_kernel()
{
    extern __shared__ float sm[];
    float* Qt = sm;                 // [64][68]  d-major (transposed), pre-scaled
    float* Kt = Qt + 64*68;         // [64][68]  d-major (transposed)
    float* Pt = Kt + 64*68;         // [64][68]  j-major P, rows contiguous
    float* Vs = Pt + 64*68;         // [64][64]  row-major (j, d)
    float* Vi = Vs + 64*64;         // [64][64]

    const int bh = blockIdx.y;           // b*NH + h
    const int i0 = blockIdx.x * 64;      // query tile
    const size_t base = (size_t)bh * NSEQ * DH;
    const int tid = threadIdx.x;
    const int tx = tid & 15, ty = tid >> 4;

    // load Q tile, transpose, pre-scale
    #pragma unroll
    for (int it = 0; it < 4; it++) {
        int idx = tid + it*256;          // 0..1023
        int r   = idx >> 4;              // 0..63
        int dg  = (idx & 15) * 4;        // 0..60
        float4 q = *(const float4*)&g_qh[base + (size_t)(i0 + r)*DH + dg];
        Qt[(dg+0)*68 + r] = q.x*ATT_SCALE;
        Qt[(dg+1)*68 + r] = q.y*ATT_SCALE;
        Qt[(dg+2)*68 + r] = q.z*ATT_SCALE;
        Qt[(dg+3)*68 + r] = q.w*ATT_SCALE;
    }

    float o1[4][4] = {}, o2[4][4] = {};
    float mrow[4], lrow[4];
    #pragma unroll
    for (int i = 0; i < 4; i++) { mrow[i] = -1e30f; lrow[i] = 0.f; }

    for (int j0 = 0; j0 < NSEQ; j0 += 64) {
        // load K (transposed) and V / V_img tiles
        #pragma unroll
        for (int it = 0; it < 4; it++) {
            int idx = tid + it*256;
            int r   = idx >> 4;
            int dg  = (idx & 15) * 4;
            float4 kv = *(const float4*)&g_kh[base + (size_t)(j0 + r)*DH + dg];
            Kt[(dg+0)*68 + r] = kv.x;
            Kt[(dg+1)*68 + r] = kv.y;
            Kt[(dg+2)*68 + r] = kv.z;
            Kt[(dg+3)*68 + r] = kv.w;
            *(float4*)&Vs[idx*4] = *(const float4*)&g_vh [base + (size_t)j0*DH + idx*4];
            *(float4*)&Vi[idx*4] = *(const float4*)&g_vih[base + (size_t)j0*DH + idx*4];
        }
        __syncthreads();

        // S = (Q*scale) @ K^T  (4x4 per thread)
        float s[4][4] = {};
        #pragma unroll 16
        for (int d = 0; d < 64; d++) {
            float4 qv = *(const float4*)&Qt[d*68 + ty*4];
            float4 kv = *(const float4*)&Kt[d*68 + tx*4];
            float qa[4] = {qv.x,qv.y,qv.z,qv.w};
            float ka[4] = {kv.x,kv.y,kv.z,kv.w};
            #pragma unroll
            for (int i = 0; i < 4; i++)
                #pragma unroll
                for (int j = 0; j < 4; j++) s[i][j] += qa[i]*ka[j];
        }

        // online softmax per row; reduce across the 16 tx-lanes (same half-warp)
        #pragma unroll
        for (int i = 0; i < 4; i++) {
            float mx = fmaxf(fmaxf(s[i][0],s[i][1]), fmaxf(s[i][2],s[i][3]));
            #pragma unroll
            for (int off = 8; off >= 1; off >>= 1)
                mx = fmaxf(mx, __shfl_xor_sync(0xffffffffu, mx, off));
            float mnew  = fmaxf(mrow[i], mx);
            float alpha = __expf(mrow[i] - mnew);
            float rs = 0.f;
            #pragma unroll
            for (int j = 0; j < 4; j++) {
                float p = __expf(s[i][j] - mnew);
                s[i][j] = p; rs += p;
            }
            #pragma unroll
            for (int off = 8; off >= 1; off >>= 1)
                rs += __shfl_xor_sync(0xffffffffu, rs, off);
            lrow[i] = lrow[i]*alpha + rs;
            mrow[i] = mnew;
            #pragma unroll
            for (int j = 0; j < 4; j++) { o1[i][j]*=alpha; o2[i][j]*=alpha; }
        }

        // write P transposed (j-major, rows contiguous) for vectorized O-gemm
        #pragma unroll
        for (int i = 0; i < 4; i++)
            #pragma unroll
            for (int j = 0; j < 4; j++)
                Pt[(4*tx + j)*68 + 4*ty + i] = s[i][j];
        __syncthreads();

        // O  += P @ V ;  O_img += P @ V_img
        #pragma unroll 8
        for (int j = 0; j < 64; j++) {
            float4 pv = *(const float4*)&Pt[j*68 + ty*4];
            float4 vv = *(const float4*)&Vs[j*64 + tx*4];
            float4 wv = *(const float4*)&Vi[j*64 + tx*4];
            float pa[4] = {pv.x,pv.y,pv.z,pv.w};
            float va[4] = {vv.x,vv.y,vv.z,vv.w};
            float wa[4] = {wv.x,wv.y,wv.z,wv.w};
            #pragma unroll
            for (int i = 0; i < 4; i++)
                #pragma unroll
                for (int c = 0; c < 4; c++) {
                    o1[i][c] += pa[i]*va[c];
                    o2[i][c] += pa[i]*wa[c];
                }
        }
        __syncthreads();
    }

    // normalize and store into merged [b][n][c] layout
    const int b = bh / NH, h = bh % NH;
    #pragma unroll
    for (int i = 0; i < 4; i++) {
        float inv = 1.0f / lrow[i];
        int n = i0 + 4*ty + i;
        size_t off = ((size_t)b*NSEQ + n)*DIMC + h*DH + 4*tx;
        *(float4*)&g_o1[off] = make_float4(o1[i][0]*inv,o1[i][1]*inv,
                                           o1[i][2]*inv,o1[i][3]*inv);
        *(float4*)&g_o2[off] = make_float4(o2[i][0]*inv,o2[i][1]*inv,
                                           o2[i][2]*inv,o2[i][3]*inv);
    }
}

// ---------------------------------------------------------------------------
extern "C" void kernel_launch(void* const* d_in, const int* in_sizes, int n_in,
                              void* d_out, int out_size)
{
    const float* q    = (const float*)d_in[0];
    const float* k    = (const float*)d_in[1];
    const float* v    = (const float*)d_in[2];
    const float* vim  = (const float*)d_in[3];
    const float* Wq   = (const float*)d_in[4];
    const float* Wk   = (const float*)d_in[5];
    const float* Wv   = (const float*)d_in[6];
    const float* Wvim = (const float*)d_in[7];
    const float* Wp   = (const float*)d_in[8];
    const float* bp   = (const float*)d_in[9];
    const float* Wpi  = (const float*)d_in[10];
    const float* bpi  = (const float*)d_in[11];

    float *qh, *kh, *vh, *vih, *o1, *o2;
    cudaGetSymbolAddress((void**)&qh,  g_qh);
    cudaGetSymbolAddress((void**)&kh,  g_kh);
    cudaGetSymbolAddress((void**)&vh,  g_vh);
    cudaGetSymbolAddress((void**)&vih, g_vih);
    cudaGetSymbolAddress((void**)&o1,  g_o1);
    cudaGetSymbolAddress((void**)&o2,  g_o2);

    dim3 pg(NH, (BATCH*NSEQ)/64);   // (12, 128)

    proj_in_kernel<<<pg, 256>>>(q,   Wq,   qh);
    proj_in_kernel<<<pg, 256>>>(k,   Wk,   kh);
    proj_in_kernel<<<pg, 256>>>(v,   Wv,   vh);
    proj_in_kernel<<<pg, 256>>>(vim, Wvim, vih);

    const size_t smem = (size_t)(3*64*68 + 2*64*64) * sizeof(float); // 84992 B
    cudaFuncSetAttribute(attn_kernel,
                         cudaFuncAttributeMaxDynamicSharedMemorySize, (int)smem);
    attn_kernel<<<dim3(NSEQ/64, BATCH*NH), 256, smem>>>();

    float* out = (float*)d_out;
    proj_out_kernel<<<pg, 256>>>(o1, Wp,  bp,  out);
    proj_out_kernel<<<pg, 256>>>(o2, Wpi, bpi, out + (size_t)BATCH*NSEQ*DIMC);
}

// round 3
// speedup vs baseline: 1.0003x; 1.0003x over previous
#include <cuda_runtime.h>

#define DIMC 768
#define NSEQ 1024
#define BATCH 8
#define NH 12
#define DH 64
#define ATT_SCALE 0.125f   // 64^-0.5

// ---------------- scratch (static device globals; no allocation) ------------
__device__ float g_qh [BATCH*NH*NSEQ*DH];   // [b][h][n][d]
__device__ float g_kh [BATCH*NH*NSEQ*DH];
__device__ float g_vh [BATCH*NH*NSEQ*DH];
__device__ float g_vih[BATCH*NH*NSEQ*DH];
__device__ float g_o1 [BATCH*NSEQ*DIMC];    // merged [b][n][c]
__device__ float g_o2 [BATCH*NSEQ*DIMC];

// ---------------------------------------------------------------------------
// Input projection: C[m,o] = sum_k in[n,b,k] * W[o,k], m = b*NSEQ+n
// in is seq-first [NSEQ, BATCH, DIMC]. Output written head-major:
// out[((b*NH+h)*NSEQ + n)*DH + d],  o = h*DH + d.
// Block: 64(m) x 64(o) tile, 256 threads, 4x4 micro-tile, K-step 16.
// ---------------------------------------------------------------------------
__global__ __launch_bounds__(256) void proj_in_kernel(
    const float* __restrict__ in, const float* __restrict__ W,
    float* __restrict__ out)
{
    __shared__ float As[16][68];
    __shared__ float Ws[16][68];
    const int h  = blockIdx.x;          // 0..11 (output 64-col tile)
    const int m0 = blockIdx.y * 64;     // row tile
    const int b  = m0 / NSEQ;
    const int n0 = m0 % NSEQ;
    const int tid = threadIdx.x;
    const int tx = tid & 15, ty = tid >> 4;
    const int lm = tid >> 2;            // 0..63
    const int lk = (tid & 3) * 4;       // 0,4,8,12

    float acc[4][4] = {};
    const float* aptr = in + ((size_t)(n0 + lm) * BATCH + b) * DIMC + lk;
    const float* wptr = W  + ((size_t)(h * DH + lm)) * DIMC + lk;

    for (int k0 = 0; k0 < DIMC; k0 += 16) {
        float4 a = *(const float4*)(aptr + k0);
        float4 w = *(const float4*)(wptr + k0);
        As[lk+0][lm]=a.x; As[lk+1][lm]=a.y; As[lk+2][lm]=a.z; As[lk+3][lm]=a.w;
        Ws[lk+0][lm]=w.x; Ws[lk+1][lm]=w.y; Ws[lk+2][lm]=w.z; Ws[lk+3][lm]=w.w;
        __syncthreads();
        #pragma unroll
        for (int k = 0; k < 16; k++) {
            float4 av = *(const float4*)&As[k][ty*4];
            float4 wv = *(const float4*)&Ws[k][tx*4];
            float ar[4] = {av.x,av.y,av.z,av.w};
            float wr[4] = {wv.x,wv.y,wv.z,wv.w};
            #pragma unroll
            for (int i = 0; i < 4; i++)
                #pragma unroll
                for (int j = 0; j < 4; j++) acc[i][j] += ar[i]*wr[j];
        }
        __syncthreads();
    }
    #pragma unroll
    for (int i = 0; i < 4; i++) {
        float4 v = make_float4(acc[i][0],acc[i][1],acc[i][2],acc[i][3]);
        *(float4*)&out[(((size_t)b*NH + h)*NSEQ + n0 + 4*ty + i)*DH + 4*tx] = v;
    }
}

// ---------------------------------------------------------------------------
// Output projection: out[m, o] = sum_k A[m,k]*W[o,k] + bias[o]
// A row-major [8192, 768], out row-major [8192, 768].
// ---------------------------------------------------------------------------
__global__ __launch_bounds__(256) void proj_out_kernel(
    const float* __restrict__ A, const float* __restrict__ W,
    const float* __restrict__ bias, float* __restrict__ out)
{
    __shared__ float As[16][68];
    __shared__ float Ws[16][68];
    const int h  = blockIdx.x;
    const int m0 = blockIdx.y * 64;
    const int tid = threadIdx.x;
    const int tx = tid & 15, ty = tid >> 4;
    const int lm = tid >> 2;
    const int lk = (tid & 3) * 4;

    float acc[4][4] = {};
    const float* aptr = A + (size_t)(m0 + lm) * DIMC + lk;
    const float* wptr = W + ((size_t)(h * DH + lm)) * DIMC + lk;

    for (int k0 = 0; k0 < DIMC; k0 += 16) {
        float4 a = *(const float4*)(aptr + k0);
        float4 w = *(const float4*)(wptr + k0);
        As[lk+0][lm]=a.x; As[lk+1][lm]=a.y; As[lk+2][lm]=a.z; As[lk+3][lm]=a.w;
        Ws[lk+0][lm]=w.x; Ws[lk+1][lm]=w.y; Ws[lk+2][lm]=w.z; Ws[lk+3][lm]=w.w;
        __syncthreads();
        #pragma unroll
        for (int k = 0; k < 16; k++) {
            float4 av = *(const float4*)&As[k][ty*4];
            float4 wv = *(const float4*)&Ws[k][tx*4];
            float ar[4] = {av.x,av.y,av.z,av.w};
            float wr[4] = {wv.x,wv.y,wv.z,wv.w};
            #pragma unroll
            for (int i = 0; i < 4; i++)
                #pragma unroll
                for (int j = 0; j < 4; j++) acc[i][j] += ar[i]*wr[j];
        }
        __syncthreads();
    }
    float4 bv = *(const float4*)&bias[h*DH + 4*tx];
    float br[4] = {bv.x,bv.y,bv.z,bv.w};
    #pragma unroll
    for (int i = 0; i < 4; i++) {
        float4 v = make_float4(acc[i][0]+br[0],acc[i][1]+br[1],
                               acc[i][2]+br[2],acc[i][3]+br[3]);
        *(float4*)&out[(size_t)(m0 + 4*ty + i)*DIMC + h*DH + 4*tx] = v;
    }
}

// ---------------------------------------------------------------------------
// Flash attention with DUAL value streams (softmax computed once, applied to
// both V and V_img). One block = one (b,h) x 64-query-row tile.
// Online softmax stats kept replicated in registers of the 16 threads that
// own each row (shuffle reductions within the 16-lane half-warp).
// ---------------------------------------------------------------------------
__global__ __launch_bounds__(256) void attn_kernel()
{
    extern __shared__ float sm[];
    float* Qt = sm;                 // [64][68]  d-major (transposed), pre-scaled
    float* Kt = Qt + 64*68;         // [64][68]  d-major (transposed)
    float* Pt = Kt + 64*68;         // [64][68]  j-major P, rows contiguous
    float* Vs = Pt + 64*68;         // [64][64]  row-major (j, d)
    float* Vi = Vs + 64*64;         // [64][64]

    const int bh = blockIdx.y;           // b*NH + h
    const int i0 = blockIdx.x * 64;      // query tile
    const size_t base = (size_t)bh * NSEQ * DH;
    const int tid = threadIdx.x;
    const int tx = tid & 15, ty = tid >> 4;

    // load Q tile, transpose, pre-scale
    #pragma unroll
    for (int it = 0; it < 4; it++) {
        int idx = tid + it*256;          // 0..1023
        int r   = idx >> 4;              // 0..63
        int dg  = (idx & 15) * 4;        // 0..60
        float4 q = *(const float4*)&g_qh[base + (size_t)(i0 + r)*DH + dg];
        Qt[(dg+0)*68 + r] = q.x*ATT_SCALE;
        Qt[(dg+1)*68 + r] = q.y*ATT_SCALE;
        Qt[(dg+2)*68 + r] = q.z*ATT_SCALE;
        Qt[(dg+3)*68 + r] = q.w*ATT_SCALE;
    }

    float o1[4][4] = {}, o2[4][4] = {};
    float mrow[4], lrow[4];
    #pragma unroll
    for (int i = 0; i < 4; i++) { mrow[i] = -1e30f; lrow[i] = 0.f; }

    for (int j0 = 0; j0 < NSEQ; j0 += 64) {
        // load K (transposed) and V / V_img tiles
        #pragma unroll
        for (int it = 0; it < 4; it++) {
            int idx = tid + it*256;
            int r   = idx >> 4;
            int dg  = (idx & 15) * 4;
            float4 kv = *(const float4*)&g_kh[base + (size_t)(j0 + r)*DH + dg];
            Kt[(dg+0)*68 + r] = kv.x;
            Kt[(dg+1)*68 + r] = kv.y;
            Kt[(dg+2)*68 + r] = kv.z;
            Kt[(dg+3)*68 + r] = kv.w;
            *(float4*)&Vs[idx*4] = *(const float4*)&g_vh [base + (size_t)j0*DH + idx*4];
            *(float4*)&Vi[idx*4] = *(const float4*)&g_vih[base + (size_t)j0*DH + idx*4];
        }
        __syncthreads();

        // S = (Q*scale) @ K^T  (4x4 per thread)
        float s[4][4] = {};
        #pragma unroll 16
        for (int d = 0; d < 64; d++) {
            float4 qv = *(const float4*)&Qt[d*68 + ty*4];
            float4 kv = *(const float4*)&Kt[d*68 + tx*4];
            float qa[4] = {qv.x,qv.y,qv.z,qv.w};
            float ka[4] = {kv.x,kv.y,kv.z,kv.w};
            #pragma unroll
            for (int i = 0; i < 4; i++)
                #pragma unroll
                for (int j = 0; j < 4; j++) s[i][j] += qa[i]*ka[j];
        }

        // online softmax per row; reduce across the 16 tx-lanes (same half-warp)
        #pragma unroll
        for (int i = 0; i < 4; i++) {
            float mx = fmaxf(fmaxf(s[i][0],s[i][1]), fmaxf(s[i][2],s[i][3]));
            #pragma unroll
            for (int off = 8; off >= 1; off >>= 1)
                mx = fmaxf(mx, __shfl_xor_sync(0xffffffffu, mx, off));
            float mnew  = fmaxf(mrow[i], mx);
            float alpha = __expf(mrow[i] - mnew);
            float rs = 0.f;
            #pragma unroll
            for (int j = 0; j < 4; j++) {
                float p = __expf(s[i][j] - mnew);
                s[i][j] = p; rs += p;
            }
            #pragma unroll
            for (int off = 8; off >= 1; off >>= 1)
                rs += __shfl_xor_sync(0xffffffffu, rs, off);
            lrow[i] = lrow[i]*alpha + rs;
            mrow[i] = mnew;
            #pragma unroll
            for (int j = 0; j < 4; j++) { o1[i][j]*=alpha; o2[i][j]*=alpha; }
        }

        // write P transposed (j-major, rows contiguous) for vectorized O-gemm
        #pragma unroll
        for (int i = 0; i < 4; i++)
            #pragma unroll
            for (int j = 0; j < 4; j++)
                Pt[(4*tx + j)*68 + 4*ty + i] = s[i][j];
        __syncthreads();

        // O  += P @ V ;  O_img += P @ V_img
        #pragma unroll 8
        for (int j = 0; j < 64; j++) {
            float4 pv = *(const float4*)&Pt[j*68 + ty*4];
            float4 vv = *(const float4*)&Vs[j*64 + tx*4];
            float4 wv = *(const float4*)&Vi[j*64 + tx*4];
            float pa[4] = {pv.x,pv.y,pv.z,pv.w};
            float va[4] = {vv.x,vv.y,vv.z,vv.w};
            float wa[4] = {wv.x,wv.y,wv.z,wv.w};
            #pragma unroll
            for (int i = 0; i < 4; i++)
                #pragma unroll
                for (int c = 0; c < 4; c++) {
                    o1[i][c] += pa[i]*va[c];
                    o2[i][c] += pa[i]*wa[c];
                }
        }
        __syncthreads();
    }

    // normalize and store into merged [b][n][c] layout
    const int b = bh / NH, h = bh % NH;
    #pragma unroll
    for (int i = 0; i < 4; i++) {
        float inv = 1.0f / lrow[i];
        int n = i0 + 4*ty + i;
        size_t off = ((size_t)b*NSEQ + n)*DIMC + h*DH + 4*tx;
        *(float4*)&g_o1[off] = make_float4(o1[i][0]*inv,o1[i][1]*inv,
                                           o1[i][2]*inv,o1[i][3]*inv);
        *(float4*)&g_o2[off] = make_float4(o2[i][0]*inv,o2[i][1]*inv,
                                           o2[i][2]*inv,o2[i][3]*inv);
    }
}

// ---------------------------------------------------------------------------
extern "C" void kernel_launch(void* const* d_in, const int* in_sizes, int n_in,
                              void* d_out, int out_size)
{
    const float* q    = (const float*)d_in[0];
    const float* k    = (const float*)d_in[1];
    const float* v    = (const float*)d_in[2];
    const float* vim  = (const float*)d_in[3];
    const float* Wq   = (const float*)d_in[4];
    const float* Wk   = (const float*)d_in[5];
    const float* Wv   = (const float*)d_in[6];
    const float* Wvim = (const float*)d_in[7];
    const float* Wp   = (const float*)d_in[8];
    const float* bp   = (const float*)d_in[9];
    const float* Wpi  = (const float*)d_in[10];
    const float* bpi  = (const float*)d_in[11];

    float *qh, *kh, *vh, *vih, *o1, *o2;
    cudaGetSymbolAddress((void**)&qh,  g_qh);
    cudaGetSymbolAddress((void**)&kh,  g_kh);
    cudaGetSymbolAddress((void**)&vh,  g_vh);
    cudaGetSymbolAddress((void**)&vih, g_vih);
    cudaGetSymbolAddress((void**)&o1,  g_o1);
    cudaGetSymbolAddress((void**)&o2,  g_o2);

    dim3 pg(NH, (BATCH*NSEQ)/64);   // (12, 128)

    proj_in_kernel<<<pg, 256>>>(q,   Wq,   qh);
    proj_in_kernel<<<pg, 256>>>(k,   Wk,   kh);
    proj_in_kernel<<<pg, 256>>>(v,   Wv,   vh);
    proj_in_kernel<<<pg, 256>>>(vim, Wvim, vih);

    const size_t smem = (size_t)(3*64*68 + 2*64*64) * sizeof(float); // 84992 B
    cudaFuncSetAttribute(attn_kernel,
                         cudaFuncAttributeMaxDynamicSharedMemorySize, (int)smem);
    attn_kernel<<<dim3(NSEQ/64, BATCH*NH), 256, smem>>>();

    float* out = (float*)d_out;
    proj_out_kernel<<<pg, 256>>>(o1, Wp,  bp,  out);
    proj_out_kernel<<<pg, 256>>>(o2, Wpi, bpi, out + (size_t)BATCH*NSEQ*DIMC);
}